// round 7
// baseline (speedup 1.0000x reference)
#include <cuda_runtime.h>
#include <math.h>
#include <stdint.h>

#define B_   2
#define T_   2048
#define HID  1024
#define NH   16
#define HD   64

// ---------------- scratch (device globals; no allocations allowed) ----------
__device__ float g_Q[B_ * NH * T_ * HD];
__device__ float g_K[B_ * NH * T_ * HD];
__device__ float g_V[B_ * NH * T_ * HD];
__device__ float g_att[B_ * T_ * HID];
__device__ float2 g_ctab[T_ * 32];            // cos/sin table [t][d]
__device__ signed char g_gmask[B_ * T_];
__device__ int g_gcnt[B_];
__device__ int g_glist[B_ * T_];

__device__ __forceinline__ uint32_t cvt_tf32(float f) {
    uint32_t r;
    asm("cvt.rna.tf32.f32 %0, %1;" : "=r"(r) : "f"(f));
    return r;
}

__device__ __forceinline__ void mma_tf32_16n8k8(
    float* c, uint32_t a0, uint32_t a1, uint32_t a2, uint32_t a3,
    uint32_t b0, uint32_t b1)
{
    asm volatile(
        "mma.sync.aligned.m16n8k8.row.col.f32.tf32.tf32.f32 "
        "{%0,%1,%2,%3}, {%4,%5,%6,%7}, {%8,%9}, {%0,%1,%2,%3};"
        : "+f"(c[0]), "+f"(c[1]), "+f"(c[2]), "+f"(c[3])
        : "r"(a0), "r"(a1), "r"(a2), "r"(a3), "r"(b0), "r"(b1));
}

// ---------------- cos/sin table + gcnt init ----------------------------------
__global__ void costab_kernel()
{
    int id = blockIdx.x * blockDim.x + threadIdx.x;   // 65536
    int t = id >> 5, j = id & 31;
    float invf = (float)exp((double)j * (-log(10000.0) / 32.0));
    float ang = (float)t * invf;
    float s, c;
    sincosf(ang, &s, &c);
    g_ctab[id] = make_float2(c, s);
}

__global__ void ginit_kernel()
{
    if (threadIdx.x < B_) g_gcnt[threadIdx.x] = 0;
}

__global__ void gmask_kernel(const int* __restrict__ ids)
{
    int idx = blockIdx.x * blockDim.x + threadIdx.x;
    if (idx >= B_ * T_) return;
    int id = ids[idx];
    bool g = (id >= 0 && id <= 2);
    g_gmask[idx] = g ? 1 : 0;
    if (g) {
        int b = idx / T_;
        int p = atomicAdd(&g_gcnt[b], 1);
        g_glist[b * T_ + p] = idx - b * T_;
    }
}

// ---------------- TF32 mma.sync GEMM, 128x256 tile, 64x64 per warp ----------
// MODE 0: C = A @ W^T + bias (row-major C).
// MODE 1: fused qkv epilogue: split into Q/K/V [B,H,T,D], RoPE on Q,K.
#define BM  128
#define BN  256
#define BK  16
#define GSTR 20                               // u32 per row (16 + 4 pad)
#define GA_BUF (BM * GSTR)                    // 2560 u32
#define GB_BUF (BN * GSTR)                    // 5120 u32
#define GS_TOTAL ((2 * GA_BUF + 2 * GB_BUF) * 4)   // 61440 B

template<int MODE>
__global__ __launch_bounds__(256, 1) void gemm_tf32_mma(
    const float* __restrict__ A, const float* __restrict__ W,
    const float* __restrict__ bias, float* __restrict__ C,
    int N, int K)
{
    extern __shared__ uint32_t su[];
    uint32_t* As = su;                        // 2 buffers of GA_BUF
    uint32_t* Bs = su + 2 * GA_BUF;           // 2 buffers of GB_BUF

    const int tid = threadIdx.x;
    const int lane = tid & 31;
    const int g   = lane >> 2;                // 0..7
    const int tig = lane & 3;                 // 0..3
    const int wid = tid >> 5;
    const int warp_m = wid >> 2;              // 0..1  (64 rows)
    const int warp_n = wid & 3;               // 0..3  (64 cols)
    const int row0 = blockIdx.y * BM;
    const int col0 = blockIdx.x * BN;

    // LDG mapping: A row = tid>>1 (k-half tid&1), B row = tid (all 16 k)
    const int arow = tid >> 1, ah = tid & 1;
    const float* Ag = A + (size_t)(row0 + arow) * K + ah * 8;
    const float* Bg = W + (size_t)(col0 + tid) * K;

    float c[4][8][4];
    #pragma unroll
    for (int mi = 0; mi < 4; mi++)
        #pragma unroll
        for (int ni = 0; ni < 8; ni++)
            #pragma unroll
            for (int r = 0; r < 4; r++) c[mi][ni][r] = 0.f;

    float4 pa[2], pb[4];
    const int nT = K / BK;

    // preload tile 0
    #pragma unroll
    for (int j = 0; j < 2; j++) pa[j] = *(const float4*)(Ag + j * 4);
    #pragma unroll
    for (int j = 0; j < 4; j++) pb[j] = *(const float4*)(Bg + j * 4);
    {
        uint32_t* as = As + arow * GSTR + ah * 8;
        uint32_t* bs = Bs + tid * GSTR;
        #pragma unroll
        for (int j = 0; j < 2; j++) {
            uint4 u = { cvt_tf32(pa[j].x), cvt_tf32(pa[j].y),
                        cvt_tf32(pa[j].z), cvt_tf32(pa[j].w) };
            *(uint4*)(as + j * 4) = u;
        }
        #pragma unroll
        for (int j = 0; j < 4; j++) {
            uint4 u = { cvt_tf32(pb[j].x), cvt_tf32(pb[j].y),
                        cvt_tf32(pb[j].z), cvt_tf32(pb[j].w) };
            *(uint4*)(bs + j * 4) = u;
        }
    }
    __syncthreads();

    for (int kt = 0; kt < nT; kt++) {
        const int buf = kt & 1;
        if (kt + 1 < nT) {
            const float* Ap = Ag + (kt + 1) * BK;
            const float* Bp = Bg + (kt + 1) * BK;
            #pragma unroll
            for (int j = 0; j < 2; j++) pa[j] = *(const float4*)(Ap + j * 4);
            #pragma unroll
            for (int j = 0; j < 4; j++) pb[j] = *(const float4*)(Bp + j * 4);
        }

        const uint32_t* As_ = As + buf * GA_BUF;
        const uint32_t* Bs_ = Bs + buf * GB_BUF;
        #pragma unroll
        for (int ks = 0; ks < 2; ks++) {
            const int k = ks * 8 + tig;
            uint32_t a[4][4], b[8][2];
            #pragma unroll
            for (int mi = 0; mi < 4; mi++) {
                int r = warp_m * 64 + mi * 16 + g;
                a[mi][0] = As_[r * GSTR + k];
                a[mi][1] = As_[(r + 8) * GSTR + k];
                a[mi][2] = As_[r * GSTR + k + 4];
                a[mi][3] = As_[(r + 8) * GSTR + k + 4];
            }
            #pragma unroll
            for (int ni = 0; ni < 8; ni++) {
                int n = warp_n * 64 + ni * 8 + g;
                b[ni][0] = Bs_[n * GSTR + k];
                b[ni][1] = Bs_[n * GSTR + k + 4];
            }
            #pragma unroll
            for (int mi = 0; mi < 4; mi++)
                #pragma unroll
                for (int ni = 0; ni < 8; ni++)
                    mma_tf32_16n8k8(c[mi][ni], a[mi][0], a[mi][1], a[mi][2], a[mi][3],
                                    b[ni][0], b[ni][1]);
        }

        if (kt + 1 < nT) {
            uint32_t* as = As + (buf ^ 1) * GA_BUF + arow * GSTR + ah * 8;
            uint32_t* bs = Bs + (buf ^ 1) * GB_BUF + tid * GSTR;
            #pragma unroll
            for (int j = 0; j < 2; j++) {
                uint4 u = { cvt_tf32(pa[j].x), cvt_tf32(pa[j].y),
                            cvt_tf32(pa[j].z), cvt_tf32(pa[j].w) };
                *(uint4*)(as + j * 4) = u;
            }
            #pragma unroll
            for (int j = 0; j < 4; j++) {
                uint4 u = { cvt_tf32(pb[j].x), cvt_tf32(pb[j].y),
                            cvt_tf32(pb[j].z), cvt_tf32(pb[j].w) };
                *(uint4*)(bs + j * 4) = u;
            }
        }
        __syncthreads();
    }

    if (MODE == 0) {
        #pragma unroll
        for (int mi = 0; mi < 4; mi++) {
            const int row = row0 + warp_m * 64 + mi * 16 + g;
            #pragma unroll
            for (int ni = 0; ni < 8; ni++) {
                const int col = col0 + warp_n * 64 + ni * 8 + 2 * tig;
                float2 v0, v1;
                v0.x = c[mi][ni][0] + bias[col];
                v0.y = c[mi][ni][1] + bias[col + 1];
                v1.x = c[mi][ni][2] + bias[col];
                v1.y = c[mi][ni][3] + bias[col + 1];
                *(float2*)(C + (size_t)row * N + col) = v0;
                *(float2*)(C + (size_t)(row + 8) * N + col) = v1;
            }
        }
    } else {
        // blockIdx.x 0..11. sec = bx>>2 (0=Q,1=K,2=V). head = (bx&3)*4 + warp_n.
        const int sec  = blockIdx.x >> 2;
        const int head = (blockIdx.x & 3) * 4 + warp_n;
        #pragma unroll
        for (int mi = 0; mi < 4; mi++) {
            const int row = row0 + warp_m * 64 + mi * 16 + g;
            const int bb = row >> 11, tt = row & (T_ - 1);
            if (sec == 2) {
                const float* bi = bias + 2 * HID + head * HD;
                float* dstb = g_V + (((size_t)(bb * NH + head)) * T_ + tt) * HD;
                #pragma unroll
                for (int ni = 0; ni < 8; ni++) {
                    const int dd = ni * 8 + 2 * tig;
                    float b0 = bi[dd], b1 = bi[dd + 1];
                    float2 v0 = { c[mi][ni][0] + b0, c[mi][ni][1] + b1 };
                    float2 v1 = { c[mi][ni][2] + b0, c[mi][ni][3] + b1 };
                    *(float2*)(dstb + dd) = v0;
                    *(float2*)(dstb + 8 * HD + dd) = v1;
                }
            } else {
                float* dstb = (sec ? g_K : g_Q)
                            + (((size_t)(bb * NH + head)) * T_ + tt) * HD;
                const float* bi = bias + sec * HID + head * HD;
                #pragma unroll
                for (int ni = 0; ni < 4; ni++) {
                    const int dd = ni * 8 + 2 * tig;      // 0..30
                    float x1a = c[mi][ni][0]     + bi[dd];
                    float x1b = c[mi][ni][1]     + bi[dd + 1];
                    float x2a = c[mi][ni + 4][0] + bi[dd + 32];
                    float x2b = c[mi][ni + 4][1] + bi[dd + 33];
                    float y1a = c[mi][ni][2]     + bi[dd];
                    float y1b = c[mi][ni][3]     + bi[dd + 1];
                    float y2a = c[mi][ni + 4][2] + bi[dd + 32];
                    float y2b = c[mi][ni + 4][3] + bi[dd + 33];
                    float2 cs0 = g_ctab[tt * 32 + dd];
                    float2 cs1 = g_ctab[tt * 32 + dd + 1];
                    float2 ds0 = g_ctab[(tt + 8) * 32 + dd];
                    float2 ds1 = g_ctab[(tt + 8) * 32 + dd + 1];
                    float2 r0 = { x1a * cs0.x - x2a * cs0.y, x1b * cs1.x - x2b * cs1.y };
                    float2 r1 = { x1a * cs0.y + x2a * cs0.x, x1b * cs1.y + x2b * cs1.x };
                    float2 r2 = { y1a * ds0.x - y2a * ds0.y, y1b * ds1.x - y2b * ds1.y };
                    float2 r3 = { y1a * ds0.y + y2a * ds0.x, y1b * ds1.y + y2b * ds1.x };
                    *(float2*)(dstb + dd) = r0;
                    *(float2*)(dstb + dd + 32) = r1;
                    *(float2*)(dstb + 8 * HD + dd) = r2;
                    *(float2*)(dstb + 8 * HD + dd + 32) = r3;
                }
            }
        }
    }
}

// ---------------- flash attention with tf32 mma, pipelined K/V ---------------
#define AQ_STR 68
#define AK_STR 68
#define AV_STR 72
#define AP_STR 68
#define AQ_OFF 0
#define AK_OFF (128 * AQ_STR)                   // 8704
#define AK_BUF (64 * AK_STR)                    // 4352
#define AV_OFF (AK_OFF + 2 * AK_BUF)            // 17408
#define AV_BUF (64 * AV_STR)                    // 4608
#define AP_OFF (AV_OFF + 2 * AV_BUF)            // 26624
#define A_SMEM_U32 (AP_OFF + 128 * AP_STR)      // 35328
#define A_SMEM_BYTES (A_SMEM_U32 * 4)           // 141312

__global__ __launch_bounds__(256) void attn_mma_kernel()
{
    extern __shared__ uint32_t smu[];
    __shared__ unsigned char gms[2][64];

    const int b   = blockIdx.z;
    const int h   = blockIdx.y;
    const int q0  = (gridDim.x - 1 - blockIdx.x) * 128;   // longest blocks first
    const int tid = threadIdx.x;
    const int lane = tid & 31;
    const int wid  = tid >> 5;
    const int g    = lane >> 2;
    const int tig  = lane & 3;

    const size_t head_off = ((size_t)b * NH + h) * T_ * HD;
    const float* Qg = g_Q + head_off;
    const float* Kg = g_K + head_off;
    const float* Vg = g_V + head_off;

    #pragma unroll
    for (int it = 0; it < 8; it++) {
        int i = tid + it * 256;
        int r = i >> 4, seg = (i & 15) << 2;
        float4 v = *(const float4*)(Qg + (size_t)(q0 + r) * HD + seg);
        uint32_t* d = smu + AQ_OFF + r * AQ_STR + seg;
        d[0] = cvt_tf32(v.x * 0.125f); d[1] = cvt_tf32(v.y * 0.125f);
        d[2] = cvt_tf32(v.z * 0.125f); d[3] = cvt_tf32(v.w * 0.125f);
    }

    float o[8][4];
    #pragma unroll
    for (int nt = 0; nt < 8; nt++)
        #pragma unroll
        for (int r = 0; r < 4; r++) o[nt][r] = 0.f;
    float m0 = -1e30f, m1 = -1e30f, l0 = 0.f, l1 = 0.f;

    const int row_l0 = wid * 16 + g;
    const int row_q0 = q0 + row_l0;
    const int row_q1 = row_q0 + 8;
    const int qmin   = q0 + wid * 16;
    const int kend   = q0 + 128;
    const int pr_row = tid >> 4, pr_seg = (tid & 15) << 2;

    float4 pk[4], pv[4];
    #pragma unroll
    for (int it = 0; it < 4; it++) {
        int r = pr_row + it * 16;
        pk[it] = *(const float4*)(Kg + (size_t)r * HD + pr_seg);
        pv[it] = *(const float4*)(Vg + (size_t)r * HD + pr_seg);
    }

    for (int t0 = 0; t0 < kend; t0 += 64) {
        const int buf = (t0 >> 6) & 1;
        #pragma unroll
        for (int it = 0; it < 4; it++) {
            int r = pr_row + it * 16;
            uint32_t* dk = smu + AK_OFF + buf * AK_BUF + r * AK_STR + pr_seg;
            uint32_t* dv = smu + AV_OFF + buf * AV_BUF + r * AV_STR + pr_seg;
            dk[0] = cvt_tf32(pk[it].x); dk[1] = cvt_tf32(pk[it].y);
            dk[2] = cvt_tf32(pk[it].z); dk[3] = cvt_tf32(pk[it].w);
            dv[0] = cvt_tf32(pv[it].x); dv[1] = cvt_tf32(pv[it].y);
            dv[2] = cvt_tf32(pv[it].z); dv[3] = cvt_tf32(pv[it].w);
        }
        if (tid < 64) gms[buf][tid] = (unsigned char)g_gmask[b * T_ + t0 + tid];
        __syncthreads();

        if (t0 + 64 < kend) {
            #pragma unroll
            for (int it = 0; it < 4; it++) {
                int r = t0 + 64 + pr_row + it * 16;
                pk[it] = *(const float4*)(Kg + (size_t)r * HD + pr_seg);
                pv[it] = *(const float4*)(Vg + (size_t)r * HD + pr_seg);
            }
        }

        const uint32_t* Kb = smu + AK_OFF + buf * AK_BUF;
        const uint32_t* Vb = smu + AV_OFF + buf * AV_BUF;

        float s[8][4];
        #pragma unroll
        for (int nt = 0; nt < 8; nt++)
            #pragma unroll
            for (int r = 0; r < 4; r++) s[nt][r] = 0.f;

        #pragma unroll
        for (int ks = 0; ks < 8; ks++) {
            const int kk = ks * 8 + tig;
            uint32_t a0 = smu[AQ_OFF + (row_l0)     * AQ_STR + kk];
            uint32_t a1 = smu[AQ_OFF + (row_l0 + 8) * AQ_STR + kk];
            uint32_t a2 = smu[AQ_OFF + (row_l0)     * AQ_STR + kk + 4];
            uint32_t a3 = smu[AQ_OFF + (row_l0 + 8) * AQ_STR + kk + 4];
            uint32_t bb[8][2];
            #pragma unroll
            for (int nt = 0; nt < 8; nt++) {
                bb[nt][0] = Kb[(nt * 8 + g) * AK_STR + kk];
                bb[nt][1] = Kb[(nt * 8 + g) * AK_STR + kk + 4];
            }
            #pragma unroll
            for (int nt = 0; nt < 8; nt++)
                mma_tf32_16n8k8(s[nt], a0, a1, a2, a3, bb[nt][0], bb[nt][1]);
        }

        const bool need_mask = (t0 + 63 > qmin);
        float rm0 = -1e30f, rm1 = -1e30f;
        #pragma unroll
        for (int nt = 0; nt < 8; nt++) {
            if (need_mask) {
                int kcol = t0 + nt * 8 + 2 * tig;
                bool gm0 = gms[buf][nt * 8 + 2 * tig] != 0;
                bool gm1 = gms[buf][nt * 8 + 2 * tig + 1] != 0;
                if (!(kcol     <= row_q0 || gm0)) s[nt][0] = -1e30f;
                if (!(kcol + 1 <= row_q0 || gm1)) s[nt][1] = -1e30f;
                if (!(kcol     <= row_q1 || gm0)) s[nt][2] = -1e30f;
                if (!(kcol + 1 <= row_q1 || gm1)) s[nt][3] = -1e30f;
            }
            rm0 = fmaxf(rm0, fmaxf(s[nt][0], s[nt][1]));
            rm1 = fmaxf(rm1, fmaxf(s[nt][2], s[nt][3]));
        }
        rm0 = fmaxf(rm0, __shfl_xor_sync(0xffffffffu, rm0, 1));
        rm0 = fmaxf(rm0, __shfl_xor_sync(0xffffffffu, rm0, 2));
        rm1 = fmaxf(rm1, __shfl_xor_sync(0xffffffffu, rm1, 1));
        rm1 = fmaxf(rm1, __shfl_xor_sync(0xffffffffu, rm1, 2));

        float mn0 = fmaxf(m0, rm0), mn1 = fmaxf(m1, rm1);
        float al0 = __expf(m0 - mn0), al1 = __expf(m1 - mn1);
        l0 *= al0; l1 *= al1;
        #pragma unroll
        for (int nt = 0; nt < 8; nt++) {
            o[nt][0] *= al0; o[nt][1] *= al0;
            o[nt][2] *= al1; o[nt][3] *= al1;
        }
        uint32_t* P0 = smu + AP_OFF + (row_l0)     * AP_STR;
        uint32_t* P1 = smu + AP_OFF + (row_l0 + 8) * AP_STR;
        #pragma unroll
        for (int nt = 0; nt < 8; nt++) {
            float p0 = __expf(s[nt][0] - mn0), p1 = __expf(s[nt][1] - mn0);
            float p2 = __expf(s[nt][2] - mn1), p3 = __expf(s[nt][3] - mn1);
            l0 += p0 + p1; l1 += p2 + p3;
            int cc = nt * 8 + 2 * tig;
            P0[cc] = cvt_tf32(p0); P0[cc + 1] = cvt_tf32(p1);
            P1[cc] = cvt_tf32(p2); P1[cc + 1] = cvt_tf32(p3);
        }
        m0 = mn0; m1 = mn1;
        __syncwarp();

        #pragma unroll
        for (int ks = 0; ks < 8; ks++) {
            const int kk = ks * 8 + tig;
            uint32_t a0 = smu[AP_OFF + (row_l0)     * AP_STR + kk];
            uint32_t a1 = smu[AP_OFF + (row_l0 + 8) * AP_STR + kk];
            uint32_t a2 = smu[AP_OFF + (row_l0)     * AP_STR + kk + 4];
            uint32_t a3 = smu[AP_OFF + (row_l0 + 8) * AP_STR + kk + 4];
            uint32_t bb[8][2];
            #pragma unroll
            for (int nt = 0; nt < 8; nt++) {
                bb[nt][0] = Vb[(ks * 8 + tig)     * AV_STR + nt * 8 + g];
                bb[nt][1] = Vb[(ks * 8 + tig + 4) * AV_STR + nt * 8 + g];
            }
            #pragma unroll
            for (int nt = 0; nt < 8; nt++)
                mma_tf32_16n8k8(o[nt], a0, a1, a2, a3, bb[nt][0], bb[nt][1]);
        }
    }

    l0 += __shfl_xor_sync(0xffffffffu, l0, 1);
    l0 += __shfl_xor_sync(0xffffffffu, l0, 2);
    l1 += __shfl_xor_sync(0xffffffffu, l1, 1);
    l1 += __shfl_xor_sync(0xffffffffu, l1, 2);

    const int ng = g_gcnt[b];
    for (int gi = 0; gi < ng; gi++) {
        int k = g_glist[b * T_ + gi];
        if (k < kend) continue;
        const float* Kr = Kg + (size_t)k * HD;
        const float* Vr = Vg + (size_t)k * HD;
        const float* q0p = Qg + (size_t)row_q0 * HD;
        const float* q1p = Qg + (size_t)row_q1 * HD;
        float s0 = 0.f, s1 = 0.f;
        #pragma unroll
        for (int d = 0; d < HD; d++) {
            float kv = __ldg(Kr + d);
            s0 = fmaf(__ldg(q0p + d), kv, s0);
            s1 = fmaf(__ldg(q1p + d), kv, s1);
        }
        s0 *= 0.125f; s1 *= 0.125f;
        float mn0 = fmaxf(m0, s0), mn1 = fmaxf(m1, s1);
        float al0 = __expf(m0 - mn0), al1 = __expf(m1 - mn1);
        float p0 = __expf(s0 - mn0), p1 = __expf(s1 - mn1);
        l0 = l0 * al0 + p0; l1 = l1 * al1 + p1;
        m0 = mn0; m1 = mn1;
        #pragma unroll
        for (int nt = 0; nt < 8; nt++) {
            int cc = nt * 8 + 2 * tig;
            float v0 = __ldg(Vr + cc), v1 = __ldg(Vr + cc + 1);
            o[nt][0] = o[nt][0] * al0 + p0 * v0;
            o[nt][1] = o[nt][1] * al0 + p0 * v1;
            o[nt][2] = o[nt][2] * al1 + p1 * v0;
            o[nt][3] = o[nt][3] * al1 + p1 * v1;
        }
    }

    float i0 = 1.f / l0, i1 = 1.f / l1;
    float* O0 = g_att + ((size_t)(b * T_ + row_q0)) * HID + h * HD;
    float* O1 = g_att + ((size_t)(b * T_ + row_q1)) * HID + h * HD;
    #pragma unroll
    for (int nt = 0; nt < 8; nt++) {
        int cc = nt * 8 + 2 * tig;
        float2 v0 = { o[nt][0] * i0, o[nt][1] * i0 };
        float2 v1 = { o[nt][2] * i1, o[nt][3] * i1 };
        *(float2*)(O0 + cc) = v0;
        *(float2*)(O1 + cc) = v1;
    }
}

// ---------------- launch -----------------------------------------------------
extern "C" void kernel_launch(void* const* d_in, const int* in_sizes, int n_in,
                              void* d_out, int out_size)
{
    (void)in_sizes; (void)n_in; (void)out_size;
    const float* x      = (const float*)d_in[0];
    const int*   ids    = (const int*)d_in[1];
    const float* qkv_w  = (const float*)d_in[2];
    const float* qkv_b  = (const float*)d_in[3];
    const float* out_w  = (const float*)d_in[4];
    const float* out_b  = (const float*)d_in[5];
    float*       out    = (float*)d_out;

    float* p_att = nullptr;
    cudaGetSymbolAddress((void**)&p_att, g_att);

    cudaFuncSetAttribute(gemm_tf32_mma<0>,
                         cudaFuncAttributeMaxDynamicSharedMemorySize, GS_TOTAL);
    cudaFuncSetAttribute(gemm_tf32_mma<1>,
                         cudaFuncAttributeMaxDynamicSharedMemorySize, GS_TOTAL);
    cudaFuncSetAttribute(attn_mma_kernel,
                         cudaFuncAttributeMaxDynamicSharedMemorySize, A_SMEM_BYTES);

    // 1. cos/sin table
    costab_kernel<<<T_ * 32 / 256, 256>>>();
    // 2-3. global-token mask
    ginit_kernel<<<1, 32>>>();
    gmask_kernel<<<(B_ * T_ + 255) / 256, 256>>>(ids);
    // 4. fused qkv GEMM + bias + RoPE + split -> g_Q/g_K/g_V
    gemm_tf32_mma<1><<<dim3(3 * HID / BN, (B_ * T_) / BM), 256, GS_TOTAL>>>(
        x, qkv_w, qkv_b, nullptr, 3 * HID, HID);
    // 5. attention
    attn_mma_kernel<<<dim3(T_ / 128, NH, B_), 256, A_SMEM_BYTES>>>();
    // 6. out = att @ out_w^T + out_b
    gemm_tf32_mma<0><<<dim3(HID / BN, (B_ * T_) / BM), 256, GS_TOTAL>>>(
        p_att, out_w, out_b, out, HID, HID);
}

// round 8
// speedup vs baseline: 1.1305x; 1.1305x over previous
#include <cuda_runtime.h>
#include <math.h>
#include <stdint.h>

#define B_   2
#define T_   2048
#define HID  1024
#define NH   16
#define HD   64

// ---------------- scratch (device globals; no allocations allowed) ----------
__device__ float g_Q[B_ * NH * T_ * HD];
__device__ float g_K[B_ * NH * T_ * HD];
__device__ float g_V[B_ * NH * T_ * HD];
__device__ float g_att[B_ * T_ * HID];
__device__ float2 g_ctab[T_ * 32];            // cos/sin table [t][d]
__device__ signed char g_gmask[B_ * T_];
__device__ int g_gcnt[B_];
__device__ int g_glist[B_ * T_];

__device__ __forceinline__ uint32_t cvt_tf32(float f) {
    uint32_t r;
    asm("cvt.rna.tf32.f32 %0, %1;" : "=r"(r) : "f"(f));
    return r;
}

__device__ __forceinline__ void mma_tf32_16n8k8(
    float* c, uint32_t a0, uint32_t a1, uint32_t a2, uint32_t a3,
    uint32_t b0, uint32_t b1)
{
    asm volatile(
        "mma.sync.aligned.m16n8k8.row.col.f32.tf32.tf32.f32 "
        "{%0,%1,%2,%3}, {%4,%5,%6,%7}, {%8,%9}, {%0,%1,%2,%3};"
        : "+f"(c[0]), "+f"(c[1]), "+f"(c[2]), "+f"(c[3])
        : "r"(a0), "r"(a1), "r"(a2), "r"(a3), "r"(b0), "r"(b1));
}

// ---------------- cos/sin table + gcnt init ----------------------------------
__global__ void costab_kernel()
{
    int id = blockIdx.x * blockDim.x + threadIdx.x;   // 65536
    int t = id >> 5, j = id & 31;
    float invf = (float)exp((double)j * (-log(10000.0) / 32.0));
    float ang = (float)t * invf;
    float s, c;
    sincosf(ang, &s, &c);
    g_ctab[id] = make_float2(c, s);
}

__global__ void ginit_kernel()
{
    if (threadIdx.x < B_) g_gcnt[threadIdx.x] = 0;
}

__global__ void gmask_kernel(const int* __restrict__ ids)
{
    int idx = blockIdx.x * blockDim.x + threadIdx.x;
    if (idx >= B_ * T_) return;
    int id = ids[idx];
    bool g = (id >= 0 && id <= 2);
    g_gmask[idx] = g ? 1 : 0;
    if (g) {
        int b = idx / T_;
        int p = atomicAdd(&g_gcnt[b], 1);
        g_glist[b * T_ + p] = idx - b * T_;
    }
}

// ---------------- TF32 mma.sync GEMM (R5 proven config) ----------------------
// MODE 0: C = A @ W^T + bias (row-major C).
// MODE 1: fused qkv epilogue: split into Q/K/V [B,H,T,D], RoPE on Q,K.
#define GS_STRIDE 36
#define GS_BUF    (128 * GS_STRIDE)
#define GS_TOTAL  (4 * GS_BUF * 4)

template<int MODE>
__global__ __launch_bounds__(256) void gemm_tf32_mma(
    const float* __restrict__ A, const float* __restrict__ W,
    const float* __restrict__ bias, float* __restrict__ C,
    int N, int K)
{
    extern __shared__ float sm[];
    float* Asm = sm;
    float* Bsm = sm + 2 * GS_BUF;

    const int tid = threadIdx.x;
    const int lane = tid & 31;
    const int wid = tid >> 5;
    const int warp_m = wid & 3;
    const int warp_n = wid >> 2;
    const int row0 = blockIdx.y * 128;
    const int col0 = blockIdx.x * 128;

    const int lrow = tid >> 1;
    const int lseg = (tid & 1) * 16;

    const float* Ag = A + (size_t)(row0 + lrow) * K + lseg;
    const float* Bg = W + (size_t)(col0 + lrow) * K + lseg;

    float c[2][8][4];
    #pragma unroll
    for (int mi = 0; mi < 2; mi++)
        #pragma unroll
        for (int ni = 0; ni < 8; ni++)
            #pragma unroll
            for (int r = 0; r < 4; r++) c[mi][ni][r] = 0.f;

    float4 pa[4], pb[4];
    const int nT = K / 32;

    #pragma unroll
    for (int j = 0; j < 4; j++) {
        pa[j] = *(const float4*)(Ag + j * 4);
        pb[j] = *(const float4*)(Bg + j * 4);
    }
    {
        uint32_t* as = (uint32_t*)(Asm) + lrow * GS_STRIDE + lseg;
        uint32_t* bs = (uint32_t*)(Bsm) + lrow * GS_STRIDE + lseg;
        #pragma unroll
        for (int j = 0; j < 4; j++) {
            uint4 ua = { cvt_tf32(pa[j].x), cvt_tf32(pa[j].y),
                         cvt_tf32(pa[j].z), cvt_tf32(pa[j].w) };
            uint4 ub = { cvt_tf32(pb[j].x), cvt_tf32(pb[j].y),
                         cvt_tf32(pb[j].z), cvt_tf32(pb[j].w) };
            *(uint4*)(as + j * 4) = ua;
            *(uint4*)(bs + j * 4) = ub;
        }
    }
    __syncthreads();

    for (int kt = 0; kt < nT; kt++) {
        const int buf = kt & 1;
        if (kt + 1 < nT) {
            const float* Ap = Ag + (kt + 1) * 32;
            const float* Bp = Bg + (kt + 1) * 32;
            #pragma unroll
            for (int j = 0; j < 4; j++) {
                pa[j] = *(const float4*)(Ap + j * 4);
                pb[j] = *(const float4*)(Bp + j * 4);
            }
        }

        const uint32_t* As_ = (const uint32_t*)(Asm + buf * GS_BUF);
        const uint32_t* Bs_ = (const uint32_t*)(Bsm + buf * GS_BUF);
        #pragma unroll
        for (int ks = 0; ks < 4; ks++) {
            const int k = ks * 8 + (lane & 3);
            uint32_t a[2][4], b[8][2];
            #pragma unroll
            for (int mi = 0; mi < 2; mi++) {
                int r = warp_m * 32 + mi * 16 + (lane >> 2);
                a[mi][0] = As_[r * GS_STRIDE + k];
                a[mi][1] = As_[(r + 8) * GS_STRIDE + k];
                a[mi][2] = As_[r * GS_STRIDE + k + 4];
                a[mi][3] = As_[(r + 8) * GS_STRIDE + k + 4];
            }
            #pragma unroll
            for (int ni = 0; ni < 8; ni++) {
                int n = warp_n * 64 + ni * 8 + (lane >> 2);
                b[ni][0] = Bs_[n * GS_STRIDE + k];
                b[ni][1] = Bs_[n * GS_STRIDE + k + 4];
            }
            #pragma unroll
            for (int mi = 0; mi < 2; mi++)
                #pragma unroll
                for (int ni = 0; ni < 8; ni++)
                    mma_tf32_16n8k8(c[mi][ni], a[mi][0], a[mi][1], a[mi][2], a[mi][3],
                                    b[ni][0], b[ni][1]);
        }

        if (kt + 1 < nT) {
            uint32_t* as = (uint32_t*)(Asm + (buf ^ 1) * GS_BUF) + lrow * GS_STRIDE + lseg;
            uint32_t* bs = (uint32_t*)(Bsm + (buf ^ 1) * GS_BUF) + lrow * GS_STRIDE + lseg;
            #pragma unroll
            for (int j = 0; j < 4; j++) {
                uint4 ua = { cvt_tf32(pa[j].x), cvt_tf32(pa[j].y),
                             cvt_tf32(pa[j].z), cvt_tf32(pa[j].w) };
                uint4 ub = { cvt_tf32(pb[j].x), cvt_tf32(pb[j].y),
                             cvt_tf32(pb[j].z), cvt_tf32(pb[j].w) };
                *(uint4*)(as + j * 4) = ua;
                *(uint4*)(bs + j * 4) = ub;
            }
        }
        __syncthreads();
    }

    if (MODE == 0) {
        #pragma unroll
        for (int mi = 0; mi < 2; mi++) {
            const int row = row0 + warp_m * 32 + mi * 16 + (lane >> 2);
            #pragma unroll
            for (int ni = 0; ni < 8; ni++) {
                const int col = col0 + warp_n * 64 + ni * 8 + 2 * (lane & 3);
                float2 v0, v1;
                v0.x = c[mi][ni][0] + bias[col];
                v0.y = c[mi][ni][1] + bias[col + 1];
                v1.x = c[mi][ni][2] + bias[col];
                v1.y = c[mi][ni][3] + bias[col + 1];
                *(float2*)(C + (size_t)row * N + col) = v0;
                *(float2*)(C + (size_t)(row + 8) * N + col) = v1;
            }
        }
    } else {
        // fused qkv epilogue: blockIdx.x 0-7 => Q, 8-15 => K, 16-23 => V
        const int sec  = blockIdx.x >> 3;
        const int colw = (blockIdx.x & 7) * 128 + warp_n * 64;  // head-aligned
        #pragma unroll
        for (int mi = 0; mi < 2; mi++) {
            const int row = row0 + warp_m * 32 + mi * 16 + (lane >> 2);
            const int bb = row >> 11, tt = row & (T_ - 1);
            if (sec == 2) {
                #pragma unroll
                for (int ni = 0; ni < 8; ni++) {
                    const int col = colw + ni * 8 + 2 * (lane & 3);
                    const int hh = col >> 6, dd = col & 63;
                    const float b0 = bias[2 * HID + col];
                    const float b1 = bias[2 * HID + col + 1];
                    float* dst = g_V + (((size_t)(bb * NH + hh)) * T_ + tt) * HD + dd;
                    float2 v0 = { c[mi][ni][0] + b0, c[mi][ni][1] + b1 };
                    float2 v1 = { c[mi][ni][2] + b0, c[mi][ni][3] + b1 };
                    *(float2*)dst = v0;
                    *(float2*)(dst + 8 * HD) = v1;
                }
            } else {
                float* dstb = sec ? g_K : g_Q;
                const float* bi = bias + sec * HID;
                #pragma unroll
                for (int ni = 0; ni < 4; ni++) {
                    const int col = colw + ni * 8 + 2 * (lane & 3);
                    const int hh = col >> 6, dd = col & 63;   // dd in [0,30]
                    float x1a = c[mi][ni][0]     + bi[col];
                    float x1b = c[mi][ni][1]     + bi[col + 1];
                    float x2a = c[mi][ni + 4][0] + bi[col + 32];
                    float x2b = c[mi][ni + 4][1] + bi[col + 33];
                    float y1a = c[mi][ni][2]     + bi[col];
                    float y1b = c[mi][ni][3]     + bi[col + 1];
                    float y2a = c[mi][ni + 4][2] + bi[col + 32];
                    float y2b = c[mi][ni + 4][3] + bi[col + 33];
                    float2 cs0 = g_ctab[tt * 32 + dd];
                    float2 cs1 = g_ctab[tt * 32 + dd + 1];
                    float2 ds0 = g_ctab[(tt + 8) * 32 + dd];
                    float2 ds1 = g_ctab[(tt + 8) * 32 + dd + 1];
                    float* dst = dstb + (((size_t)(bb * NH + hh)) * T_ + tt) * HD + dd;
                    float2 r0 = { x1a * cs0.x - x2a * cs0.y, x1b * cs1.x - x2b * cs1.y };
                    float2 r1 = { x1a * cs0.y + x2a * cs0.x, x1b * cs1.y + x2b * cs1.x };
                    float2 r2 = { y1a * ds0.x - y2a * ds0.y, y1b * ds1.x - y2b * ds1.y };
                    float2 r3 = { y1a * ds0.y + y2a * ds0.x, y1b * ds1.y + y2b * ds1.x };
                    *(float2*)dst = r0;
                    *(float2*)(dst + 32) = r1;
                    *(float2*)(dst + 8 * HD) = r2;
                    *(float2*)(dst + 8 * HD + 32) = r3;
                }
            }
        }
    }
}

// ---------------- flash attention: single K/V buffer -> 2 CTAs/SM ------------
// Block = 128 q rows of one (b,h); 8 warps, 16 rows/warp; key tiles of 64.
// Register prefetch covers LDG latency; SMEM 105.5 KB -> 2 CTAs/SM.
#define AQ_STR 68
#define AK_STR 68
#define AV_STR 72
#define AP_STR 68
#define AQ_OFF 0
#define AK_OFF (128 * AQ_STR)                   // 8704
#define AV_OFF (AK_OFF + 64 * AK_STR)           // 13056
#define AP_OFF (AV_OFF + 64 * AV_STR)           // 17664
#define A_SMEM_U32 (AP_OFF + 128 * AP_STR)      // 26368
#define A_SMEM_BYTES (A_SMEM_U32 * 4)           // 105472

__global__ __launch_bounds__(256, 2) void attn_mma_kernel()
{
    extern __shared__ uint32_t smu[];
    __shared__ unsigned char gms[64];

    const int b   = blockIdx.z;
    const int h   = blockIdx.y;
    const int q0  = (gridDim.x - 1 - blockIdx.x) * 128;   // longest blocks first
    const int tid = threadIdx.x;
    const int lane = tid & 31;
    const int wid  = tid >> 5;
    const int g    = lane >> 2;
    const int tig  = lane & 3;

    const size_t head_off = ((size_t)b * NH + h) * T_ * HD;
    const float* Qg = g_Q + head_off;
    const float* Kg = g_K + head_off;
    const float* Vg = g_V + head_off;

    #pragma unroll
    for (int it = 0; it < 8; it++) {
        int i = tid + it * 256;
        int r = i >> 4, seg = (i & 15) << 2;
        float4 v = *(const float4*)(Qg + (size_t)(q0 + r) * HD + seg);
        uint32_t* d = smu + AQ_OFF + r * AQ_STR + seg;
        d[0] = cvt_tf32(v.x * 0.125f); d[1] = cvt_tf32(v.y * 0.125f);
        d[2] = cvt_tf32(v.z * 0.125f); d[3] = cvt_tf32(v.w * 0.125f);
    }

    float o[8][4];
    #pragma unroll
    for (int nt = 0; nt < 8; nt++)
        #pragma unroll
        for (int r = 0; r < 4; r++) o[nt][r] = 0.f;
    float m0 = -1e30f, m1 = -1e30f, l0 = 0.f, l1 = 0.f;

    const int row_l0 = wid * 16 + g;
    const int row_q0 = q0 + row_l0;
    const int row_q1 = row_q0 + 8;
    const int qmin   = q0 + wid * 16;
    const int kend   = q0 + 128;
    const int pr_row = tid >> 4, pr_seg = (tid & 15) << 2;

    // register prefetch of tile 0
    float4 pk[4], pv[4];
    #pragma unroll
    for (int it = 0; it < 4; it++) {
        int r = pr_row + it * 16;
        pk[it] = *(const float4*)(Kg + (size_t)r * HD + pr_seg);
        pv[it] = *(const float4*)(Vg + (size_t)r * HD + pr_seg);
    }

    for (int t0 = 0; t0 < kend; t0 += 64) {
        // store prefetched K/V (tf32) into the single smem buffer
        #pragma unroll
        for (int it = 0; it < 4; it++) {
            int r = pr_row + it * 16;
            uint32_t* dk = smu + AK_OFF + r * AK_STR + pr_seg;
            uint32_t* dv = smu + AV_OFF + r * AV_STR + pr_seg;
            dk[0] = cvt_tf32(pk[it].x); dk[1] = cvt_tf32(pk[it].y);
            dk[2] = cvt_tf32(pk[it].z); dk[3] = cvt_tf32(pk[it].w);
            dv[0] = cvt_tf32(pv[it].x); dv[1] = cvt_tf32(pv[it].y);
            dv[2] = cvt_tf32(pv[it].z); dv[3] = cvt_tf32(pv[it].w);
        }
        if (tid < 64) gms[tid] = (unsigned char)g_gmask[b * T_ + t0 + tid];
        __syncthreads();

        // prefetch next tile (overlaps QK/softmax/PV below)
        if (t0 + 64 < kend) {
            #pragma unroll
            for (int it = 0; it < 4; it++) {
                int r = t0 + 64 + pr_row + it * 16;
                pk[it] = *(const float4*)(Kg + (size_t)r * HD + pr_seg);
                pv[it] = *(const float4*)(Vg + (size_t)r * HD + pr_seg);
            }
        }

        const uint32_t* Kb = smu + AK_OFF;
        const uint32_t* Vb = smu + AV_OFF;

        // ---- QK^T ----
        float s[8][4];
        #pragma unroll
        for (int nt = 0; nt < 8; nt++)
            #pragma unroll
            for (int r = 0; r < 4; r++) s[nt][r] = 0.f;

        #pragma unroll
        for (int ks = 0; ks < 8; ks++) {
            const int kk = ks * 8 + tig;
            uint32_t a0 = smu[AQ_OFF + (row_l0)     * AQ_STR + kk];
            uint32_t a1 = smu[AQ_OFF + (row_l0 + 8) * AQ_STR + kk];
            uint32_t a2 = smu[AQ_OFF + (row_l0)     * AQ_STR + kk + 4];
            uint32_t a3 = smu[AQ_OFF + (row_l0 + 8) * AQ_STR + kk + 4];
            uint32_t bb[8][2];
            #pragma unroll
            for (int nt = 0; nt < 8; nt++) {
                bb[nt][0] = Kb[(nt * 8 + g) * AK_STR + kk];
                bb[nt][1] = Kb[(nt * 8 + g) * AK_STR + kk + 4];
            }
            #pragma unroll
            for (int nt = 0; nt < 8; nt++)
                mma_tf32_16n8k8(s[nt], a0, a1, a2, a3, bb[nt][0], bb[nt][1]);
        }

        // ---- mask + online softmax ----
        const bool need_mask = (t0 + 63 > qmin);
        float rm0 = -1e30f, rm1 = -1e30f;
        #pragma unroll
        for (int nt = 0; nt < 8; nt++) {
            if (need_mask) {
                int kcol = t0 + nt * 8 + 2 * tig;
                bool gm0 = gms[nt * 8 + 2 * tig] != 0;
                bool gm1 = gms[nt * 8 + 2 * tig + 1] != 0;
                if (!(kcol     <= row_q0 || gm0)) s[nt][0] = -1e30f;
                if (!(kcol + 1 <= row_q0 || gm1)) s[nt][1] = -1e30f;
                if (!(kcol     <= row_q1 || gm0)) s[nt][2] = -1e30f;
                if (!(kcol + 1 <= row_q1 || gm1)) s[nt][3] = -1e30f;
            }
            rm0 = fmaxf(rm0, fmaxf(s[nt][0], s[nt][1]));
            rm1 = fmaxf(rm1, fmaxf(s[nt][2], s[nt][3]));
        }
        rm0 = fmaxf(rm0, __shfl_xor_sync(0xffffffffu, rm0, 1));
        rm0 = fmaxf(rm0, __shfl_xor_sync(0xffffffffu, rm0, 2));
        rm1 = fmaxf(rm1, __shfl_xor_sync(0xffffffffu, rm1, 1));
        rm1 = fmaxf(rm1, __shfl_xor_sync(0xffffffffu, rm1, 2));

        float mn0 = fmaxf(m0, rm0), mn1 = fmaxf(m1, rm1);
        float al0 = __expf(m0 - mn0), al1 = __expf(m1 - mn1);
        l0 *= al0; l1 *= al1;
        #pragma unroll
        for (int nt = 0; nt < 8; nt++) {
            o[nt][0] *= al0; o[nt][1] *= al0;
            o[nt][2] *= al1; o[nt][3] *= al1;
        }
        uint32_t* P0 = smu + AP_OFF + (row_l0)     * AP_STR;
        uint32_t* P1 = smu + AP_OFF + (row_l0 + 8) * AP_STR;
        #pragma unroll
        for (int nt = 0; nt < 8; nt++) {
            float p0 = __expf(s[nt][0] - mn0), p1 = __expf(s[nt][1] - mn0);
            float p2 = __expf(s[nt][2] - mn1), p3 = __expf(s[nt][3] - mn1);
            l0 += p0 + p1; l1 += p2 + p3;
            int cc = nt * 8 + 2 * tig;
            P0[cc] = cvt_tf32(p0); P0[cc + 1] = cvt_tf32(p1);
            P1[cc] = cvt_tf32(p2); P1[cc + 1] = cvt_tf32(p3);
        }
        m0 = mn0; m1 = mn1;
        __syncwarp();          // P is warp-private

        // ---- PV: O += P @ V ----
        #pragma unroll
        for (int ks = 0; ks < 8; ks++) {
            const int kk = ks * 8 + tig;
            uint32_t a0 = smu[AP_OFF + (row_l0)     * AP_STR + kk];
            uint32_t a1 = smu[AP_OFF + (row_l0 + 8) * AP_STR + kk];
            uint32_t a2 = smu[AP_OFF + (row_l0)     * AP_STR + kk + 4];
            uint32_t a3 = smu[AP_OFF + (row_l0 + 8) * AP_STR + kk + 4];
            uint32_t bb[8][2];
            #pragma unroll
            for (int nt = 0; nt < 8; nt++) {
                bb[nt][0] = Vb[(ks * 8 + tig)     * AV_STR + nt * 8 + g];
                bb[nt][1] = Vb[(ks * 8 + tig + 4) * AV_STR + nt * 8 + g];
            }
            #pragma unroll
            for (int nt = 0; nt < 8; nt++)
                mma_tf32_16n8k8(o[nt], a0, a1, a2, a3, bb[nt][0], bb[nt][1]);
        }
        __syncthreads();       // PV done before next tile overwrites K/V
    }

    l0 += __shfl_xor_sync(0xffffffffu, l0, 1);
    l0 += __shfl_xor_sync(0xffffffffu, l0, 2);
    l1 += __shfl_xor_sync(0xffffffffu, l1, 1);
    l1 += __shfl_xor_sync(0xffffffffu, l1, 2);

    // tail: rare global tokens beyond kend
    const int ng = g_gcnt[b];
    for (int gi = 0; gi < ng; gi++) {
        int k = g_glist[b * T_ + gi];
        if (k < kend) continue;
        const float* Kr = Kg + (size_t)k * HD;
        const float* Vr = Vg + (size_t)k * HD;
        const float* q0p = Qg + (size_t)row_q0 * HD;
        const float* q1p = Qg + (size_t)row_q1 * HD;
        float s0 = 0.f, s1 = 0.f;
        #pragma unroll
        for (int d = 0; d < HD; d++) {
            float kv = __ldg(Kr + d);
            s0 = fmaf(__ldg(q0p + d), kv, s0);
            s1 = fmaf(__ldg(q1p + d), kv, s1);
        }
        s0 *= 0.125f; s1 *= 0.125f;
        float mn0 = fmaxf(m0, s0), mn1 = fmaxf(m1, s1);
        float al0 = __expf(m0 - mn0), al1 = __expf(m1 - mn1);
        float p0 = __expf(s0 - mn0), p1 = __expf(s1 - mn1);
        l0 = l0 * al0 + p0; l1 = l1 * al1 + p1;
        m0 = mn0; m1 = mn1;
        #pragma unroll
        for (int nt = 0; nt < 8; nt++) {
            int cc = nt * 8 + 2 * tig;
            float v0 = __ldg(Vr + cc), v1 = __ldg(Vr + cc + 1);
            o[nt][0] = o[nt][0] * al0 + p0 * v0;
            o[nt][1] = o[nt][1] * al0 + p0 * v1;
            o[nt][2] = o[nt][2] * al1 + p1 * v0;
            o[nt][3] = o[nt][3] * al1 + p1 * v1;
        }
    }

    float i0 = 1.f / l0, i1 = 1.f / l1;
    float* O0 = g_att + ((size_t)(b * T_ + row_q0)) * HID + h * HD;
    float* O1 = g_att + ((size_t)(b * T_ + row_q1)) * HID + h * HD;
    #pragma unroll
    for (int nt = 0; nt < 8; nt++) {
        int cc = nt * 8 + 2 * tig;
        float2 v0 = { o[nt][0] * i0, o[nt][1] * i0 };
        float2 v1 = { o[nt][2] * i1, o[nt][3] * i1 };
        *(float2*)(O0 + cc) = v0;
        *(float2*)(O1 + cc) = v1;
    }
}

// ---------------- launch -----------------------------------------------------
extern "C" void kernel_launch(void* const* d_in, const int* in_sizes, int n_in,
                              void* d_out, int out_size)
{
    (void)in_sizes; (void)n_in; (void)out_size;
    const float* x      = (const float*)d_in[0];
    const int*   ids    = (const int*)d_in[1];
    const float* qkv_w  = (const float*)d_in[2];
    const float* qkv_b  = (const float*)d_in[3];
    const float* out_w  = (const float*)d_in[4];
    const float* out_b  = (const float*)d_in[5];
    float*       out    = (float*)d_out;

    float* p_att = nullptr;
    cudaGetSymbolAddress((void**)&p_att, g_att);

    cudaFuncSetAttribute(gemm_tf32_mma<0>,
                         cudaFuncAttributeMaxDynamicSharedMemorySize, GS_TOTAL);
    cudaFuncSetAttribute(gemm_tf32_mma<1>,
                         cudaFuncAttributeMaxDynamicSharedMemorySize, GS_TOTAL);
    cudaFuncSetAttribute(attn_mma_kernel,
                         cudaFuncAttributeMaxDynamicSharedMemorySize, A_SMEM_BYTES);

    // 1. cos/sin table
    costab_kernel<<<T_ * 32 / 256, 256>>>();
    // 2-3. global-token mask
    ginit_kernel<<<1, 32>>>();
    gmask_kernel<<<(B_ * T_ + 255) / 256, 256>>>(ids);
    // 4. fused qkv GEMM + bias + RoPE + split -> g_Q/g_K/g_V
    gemm_tf32_mma<1><<<dim3(3 * HID / 128, (B_ * T_) / 128), 256, GS_TOTAL>>>(
        x, qkv_w, qkv_b, nullptr, 3 * HID, HID);
    // 5. attention
    attn_mma_kernel<<<dim3(T_ / 128, NH, B_), 256, A_SMEM_BYTES>>>();
    // 6. out = att @ out_w^T + out_b
    gemm_tf32_mma<0><<<dim3(HID / 128, (B_ * T_) / 128), 256, GS_TOTAL>>>(
        p_att, out_w, out_b, out, HID, HID);
}